// round 17
// baseline (speedup 1.0000x reference)
#include <cuda_runtime.h>
#include <cuda_bf16.h>

// loss = -(1/B) * sum_b [ 1 / (sum_j sigmoid(x[b,j] - x[b,0]) + 0.5) ]
// B = 32, N = 2048. Only row i=0 of the reference's [B,N,N] pair matrix is
// used, so compute the O(B*N) reduction directly.
//
// Structure (measured-best, R14/R16) with the per-warp chain halved again:
//  - node A zeroes out[0], fences, triggers programmatic launch completion
//    (re-zeroed every replay -> graph-replay safe).
//  - node B (ProgrammaticStreamSerialization): 32 blocks x 1024 threads,
//    ONE float2 per thread (2-sigmoid dependent chain, ~45 cyc), per-thread
//    sum quantized at 2^19 (per-thread <= 2^20, block <= 2^30: int32-safe),
//    redux.sync.add.s32 warp reduce (redux.f32 illegal on sm_103, R10),
//    smem[32] + one bar, warp 0 does one full-warp LDS + one redux.
//    tid 0: cudaGridDependencySynchronize() (init is ~instant) then
//    fire-and-forget atomicAdd(out, part) — return unused -> REDG, no
//    ATOMG-return wait on any block's tail.
//  - expf/__fdividef kept over tanh.approx: tanh's ~2^-11 systematic error
//    across 2048 terms could reach ~5e-4 rel, too close to the 1e-3 gate.

#define RB 32
#define TQ_SCALE 524288.0f        /* 2^19 */
#define TQ_INV   (1.0f / 524288.0f)

static __global__ void rankloss_init(float* __restrict__ out) {
    out[0] = 0.0f;
    __threadfence();
    cudaTriggerProgrammaticLaunchCompletion();
}

static __global__ void __launch_bounds__(1024) rankloss_main(
    const float* __restrict__ x, float* __restrict__ out, float inv_B)
{
    const int b   = blockIdx.x;
    const int tid = threadIdx.x;
    const float* row = x + (size_t)b * 2048;

    const float x0 = __ldg(row);

    // 2048 floats = 1024 float2; 1024 threads -> exactly one load each.
    const float2* row2 = reinterpret_cast<const float2*>(row);
    float2 v = __ldg(row2 + tid);

    // sigmoid(v - x0) = 1 / (1 + exp(x0 - v)); two independent chains.
    float s0 = __fdividef(1.0f, 1.0f + __expf(x0 - v.x));
    float s1 = __fdividef(1.0f, 1.0f + __expf(x0 - v.y));
    float s = s0 + s1;  // in (0, 2]

    // Quantize (si <= 2^20, warp sum <= 2^25, block sum <= 2^30: int32-safe),
    // one-instruction warp reduce.
    int si = __float2int_rn(s * TQ_SCALE);
    int w  = __reduce_add_sync(0xFFFFFFFFu, si);

    __shared__ int warp_sums[32];
    const int warp = tid >> 5;
    const int lane = tid & 31;
    if (lane == 0) warp_sums[warp] = w;
    __syncthreads();

    if (warp == 0) {
        // 32 warps -> one full-warp load + one redux, no masking needed.
        int ti = __reduce_add_sync(0xFFFFFFFFu, warp_sums[lane]);

        if (lane == 0) {
            float t = (float)ti * TQ_INV;               // row sum
            float part = -(1.0f / (t + 0.5f)) * inv_B;  // -rr/32

            // PDL: wait for node A's zero (normally already satisfied),
            // then fire-and-forget accumulate (return unused -> REDG).
            cudaGridDependencySynchronize();
            atomicAdd(out, part);
        }
    }
}

extern "C" void kernel_launch(void* const* d_in, const int* in_sizes, int n_in,
                              void* d_out, int out_size) {
    const float* x = (const float*)d_in[0];
    float* out = (float*)d_out;

    const int total = in_sizes[0];   // B * N = 65536
    const int N = 2048;
    const int B = total / N;         // 32 == RB

    rankloss_init<<<1, 1>>>(out);

    cudaLaunchConfig_t cfg = {};
    cfg.gridDim  = dim3((unsigned)B, 1, 1);
    cfg.blockDim = dim3(1024, 1, 1);
    cfg.dynamicSmemBytes = 0;
    cfg.stream = 0;  // legacy default stream, same as <<<>>> above
    cudaLaunchAttribute attr[1];
    attr[0].id = cudaLaunchAttributeProgrammaticStreamSerialization;
    attr[0].val.programmaticStreamSerializationAllowed = 1;
    cfg.attrs = attr;
    cfg.numAttrs = 1;

    float inv_B = 1.0f / (float)B;
    cudaLaunchKernelEx(&cfg, rankloss_main, x, out, inv_B);
}